// round 3
// baseline (speedup 1.0000x reference)
#include <cuda_runtime.h>
#include <cuda_bf16.h>
#include <math_constants.h>

// Problem constants (fixed by the dataset)
#define MAXN 50000
#define MAXE 1600000
#define DIN 128
#define HC 64            // 2 heads * 32 channels

// -------- device scratch (no runtime allocation allowed) --------
__device__ float g_q[MAXN * HC];
__device__ float g_k[MAXN * HC];
__device__ float g_v[MAXN * HC];
__device__ int   g_cnt[MAXN];
__device__ int   g_cur[MAXN];
__device__ int   g_roff[MAXN + 1];
__device__ int   g_src[MAXE];

__device__ __forceinline__ float elu1(float x) {
    return x > 0.0f ? x : (__expf(x) - 1.0f);
}

// ============================================================
// Kernel 1: fused ELU + 4 GEMMs (q,k,v,skip).
// Block: 256 threads, tile = 64 nodes x 256 output cols
// (cols = [q(64) | k(64) | v(64) | skip(64)]).
// Static smem: xs[64][128] (32KB) + ws chunk [16][256] (16KB) = 48KB.
// d-loop in chunks of 16; warp w owns nodes w*8..w*8+7, lane tx owns
// cols tx*8..tx*8+7.
// ============================================================
__global__ void __launch_bounds__(256, 1)
gemm_qkvs_kernel(const float* __restrict__ x,
                 const float* __restrict__ Wq, const float* __restrict__ bq,
                 const float* __restrict__ Wk, const float* __restrict__ bk,
                 const float* __restrict__ Wv, const float* __restrict__ bv,
                 const float* __restrict__ Ws, const float* __restrict__ bs,
                 float* __restrict__ oskip, int Nn)
{
    __shared__ __align__(16) float xs[64 * DIN];    // 32 KB
    __shared__ __align__(16) float ws[16 * 256];    // 16 KB
    float4* xs4 = (float4*)xs;
    float4* ws4 = (float4*)ws;

    const int tid = threadIdx.x;
    const int node0 = blockIdx.x * 64;

    // ---- stage x tile with ELU (once) ----
    for (int i = tid; i < (64 * DIN) / 4; i += 256) { // 2048 float4
        int r  = i >> 5;              // 32 float4 per row
        int c4 = i & 31;
        int n  = node0 + r;
        float4 val;
        if (n < Nn) {
            val = ((const float4*)x)[(size_t)n * 32 + c4];
            val.x = elu1(val.x); val.y = elu1(val.y);
            val.z = elu1(val.z); val.w = elu1(val.w);
        } else {
            val = make_float4(0.f, 0.f, 0.f, 0.f);
        }
        xs4[r * 32 + c4] = val;
    }

    // per-thread fixed weight-load assignment:
    // float4 column index c4 = tid & 63 (constant: 256 % 64 == 0)
    const int c4   = tid & 63;        // 0..63 across the 256-col tile
    const int lmat = c4 >> 4;         // which matrix this thread loads
    const int lw4  = c4 & 15;         // float4 col within that matrix
    const float4* Wsel4 =
        (const float4*)((lmat == 0) ? Wq : (lmat == 1) ? Wk :
                        (lmat == 2) ? Wv : Ws);

    const int w  = tid >> 5;   // warp 0..7 -> node group
    const int tx = tid & 31;   // lane -> col group
    const int tx2 = tx * 2;    // float4 index into ws row

    float acc[8][8];
    #pragma unroll
    for (int i = 0; i < 8; i++)
        #pragma unroll
        for (int j = 0; j < 8; j++) acc[i][j] = 0.0f;

    for (int d0 = 0; d0 < DIN; d0 += 16) {
        __syncthreads();
        // load W rows d0..d0+15 for all 4 matrices: ws[dd][mat*64+c]
        #pragma unroll
        for (int j = 0; j < 4; j++) {
            int dd = (tid >> 6) + 4 * j;         // 0..15
            ws4[dd * 64 + c4] = Wsel4[(d0 + dd) * 16 + lw4];
        }
        __syncthreads();

        #pragma unroll
        for (int dq = 0; dq < 16; dq += 4) {
            float4 xv[8];
            #pragma unroll
            for (int i = 0; i < 8; i++)
                xv[i] = xs4[(w * 8 + i) * 32 + ((d0 + dq) >> 2)];
            #pragma unroll
            for (int dd = 0; dd < 4; dd++) {
                float4 w0 = ws4[(dq + dd) * 64 + tx2];
                float4 w1 = ws4[(dq + dd) * 64 + tx2 + 1];
                #pragma unroll
                for (int i = 0; i < 8; i++) {
                    float xv_s = (dd == 0) ? xv[i].x :
                                 (dd == 1) ? xv[i].y :
                                 (dd == 2) ? xv[i].z : xv[i].w;
                    acc[i][0] = fmaf(xv_s, w0.x, acc[i][0]);
                    acc[i][1] = fmaf(xv_s, w0.y, acc[i][1]);
                    acc[i][2] = fmaf(xv_s, w0.z, acc[i][2]);
                    acc[i][3] = fmaf(xv_s, w0.w, acc[i][3]);
                    acc[i][4] = fmaf(xv_s, w1.x, acc[i][4]);
                    acc[i][5] = fmaf(xv_s, w1.y, acc[i][5]);
                    acc[i][6] = fmaf(xv_s, w1.z, acc[i][6]);
                    acc[i][7] = fmaf(xv_s, w1.w, acc[i][7]);
                }
            }
        }
    }

    // ---- bias + store ----
    const int c0  = tx * 8;
    const int mat = c0 >> 6;     // 0=q,1=k,2=v,3=skip
    const int cm  = c0 & 63;

    const float* bptr;
    float* dptr;
    if      (mat == 0) { bptr = bq; dptr = g_q; }
    else if (mat == 1) { bptr = bk; dptr = g_k; }
    else if (mat == 2) { bptr = bv; dptr = g_v; }
    else               { bptr = bs; dptr = oskip; }

    float4 b0 = ((const float4*)(bptr + cm))[0];
    float4 b1 = ((const float4*)(bptr + cm))[1];

    #pragma unroll
    for (int i = 0; i < 8; i++) {
        int n = node0 + w * 8 + i;
        if (n < Nn) {
            float4 r0 = make_float4(acc[i][0] + b0.x, acc[i][1] + b0.y,
                                    acc[i][2] + b0.z, acc[i][3] + b0.w);
            float4 r1 = make_float4(acc[i][4] + b1.x, acc[i][5] + b1.y,
                                    acc[i][6] + b1.z, acc[i][7] + b1.w);
            float4* dst = (float4*)(dptr + (size_t)n * HC + cm);
            dst[0] = r0;
            dst[1] = r1;
        }
    }
}

// ============================================================
// CSR build kernels (edge_index is int32: row 0 = src, row 1 = dst)
// ============================================================
__global__ void zero_counts_kernel(int Nn)
{
    int i = blockIdx.x * blockDim.x + threadIdx.x;
    if (i < Nn) g_cnt[i] = 0;
}

__global__ void hist_kernel(const int* __restrict__ ei, int Ee)
{
    int e = blockIdx.x * blockDim.x + threadIdx.x;
    if (e < Ee) {
        int dst = ei[Ee + e];
        atomicAdd(&g_cnt[dst], 1);
    }
}

// single block of 1024 threads: exclusive scan of g_cnt -> g_roff, g_cur
__global__ void scan_kernel(int Nn)
{
    __shared__ int sums[1024];
    const int t = threadIdx.x;
    const int ch = (Nn + 1023) / 1024;
    const int lo = t * ch;
    const int hi = min(lo + ch, Nn);

    int local = 0;
    for (int i = lo; i < hi; i++) local += g_cnt[i];
    sums[t] = local;
    __syncthreads();

    // inclusive Hillis-Steele scan over 1024 partials
    for (int off = 1; off < 1024; off <<= 1) {
        int vprev = (t >= off) ? sums[t - off] : 0;
        __syncthreads();
        sums[t] += vprev;
        __syncthreads();
    }

    int run = (t > 0) ? sums[t - 1] : 0;   // exclusive base for this chunk
    for (int i = lo; i < hi; i++) {
        g_roff[i] = run;
        g_cur[i]  = run;
        run += g_cnt[i];
    }
    if (t == 0) g_roff[Nn] = sums[1023];
}

__global__ void scatter_kernel(const int* __restrict__ ei, int Ee)
{
    int e = blockIdx.x * blockDim.x + threadIdx.x;
    if (e < Ee) {
        int src = ei[e];
        int dst = ei[Ee + e];
        int pos = atomicAdd(&g_cur[dst], 1);
        g_src[pos] = src;
    }
}

// ============================================================
// Kernel 3: warp-per-node online-softmax attention.
// lane l: head h = l>>4, channels c = 2*(l&15), 2*(l&15)+1 (float2).
// dot(q,k) per head via 16-lane butterfly reduce.
// out[n] += acc/den (out already holds skip GEMM result).
// ============================================================
__global__ void __launch_bounds__(256)
attn_kernel(float* __restrict__ out, int Nn)
{
    const int warp = (blockIdx.x * blockDim.x + threadIdx.x) >> 5;
    if (warp >= Nn) return;
    const int n = warp;
    const int lane = threadIdx.x & 31;
    const int base = (lane >> 4) * 32 + (lane & 15) * 2;   // offset in 64-float row

    const float2 qv = *(const float2*)(g_q + (size_t)n * HC + base);

    float m = -CUDART_INF_F;
    float den = 0.0f;
    float2 acc = make_float2(0.0f, 0.0f);

    const int e0 = g_roff[n];
    const int e1 = g_roff[n + 1];

    for (int e = e0; e < e1; e++) {
        const int s = g_src[e];
        const float2 kv = *(const float2*)(g_k + (size_t)s * HC + base);
        float p = qv.x * kv.x + qv.y * kv.y;
        p += __shfl_xor_sync(0xffffffffu, p, 8);
        p += __shfl_xor_sync(0xffffffffu, p, 4);
        p += __shfl_xor_sync(0xffffffffu, p, 2);
        p += __shfl_xor_sync(0xffffffffu, p, 1);
        const float alpha = p * 0.17677669529663687f;   // 1/sqrt(32)

        const float nm    = fmaxf(m, alpha);
        const float scale = __expf(m - nm);             // first iter: exp(-inf)=0
        const float wgt   = __expf(alpha - nm);
        den = den * scale + wgt;

        const float2 vv = *(const float2*)(g_v + (size_t)s * HC + base);
        acc.x = acc.x * scale + wgt * vv.x;
        acc.y = acc.y * scale + wgt * vv.y;
        m = nm;
    }

    if (den > 0.0f) {
        const float inv = 1.0f / den;
        float2* o = (float2*)(out + (size_t)n * HC + base);
        float2 cur = *o;
        cur.x += acc.x * inv;
        cur.y += acc.y * inv;
        *o = cur;
    }
}

// ============================================================
// Launcher — kernel launches ONLY (graph-capture safe).
// ============================================================
extern "C" void kernel_launch(void* const* d_in, const int* in_sizes, int n_in,
                              void* d_out, int out_size)
{
    const float* x   = (const float*)d_in[0];
    const int*   ei  = (const int*)d_in[1];     // int32! (jax x64 disabled)
    const float* Wq  = (const float*)d_in[2];
    const float* bq  = (const float*)d_in[3];
    const float* Wk  = (const float*)d_in[4];
    const float* bk  = (const float*)d_in[5];
    const float* Wv  = (const float*)d_in[6];
    const float* bv  = (const float*)d_in[7];
    const float* Wsk = (const float*)d_in[8];
    const float* bsk = (const float*)d_in[9];
    float* out = (float*)d_out;

    const int Nn = in_sizes[0] / DIN;
    const int Ee = in_sizes[1] / 2;

    // GEMMs: writes g_q, g_k, g_v and the skip term into d_out
    gemm_qkvs_kernel<<<(Nn + 63) / 64, 256>>>(
        x, Wq, bq, Wk, bk, Wv, bv, Wsk, bsk, out, Nn);

    // CSR build by destination node
    zero_counts_kernel<<<(Nn + 255) / 256, 256>>>(Nn);
    hist_kernel<<<(Ee + 255) / 256, 256>>>(ei, Ee);
    scan_kernel<<<1, 1024>>>(Nn);
    scatter_kernel<<<(Ee + 255) / 256, 256>>>(ei, Ee);

    // attention: one warp per destination node, accumulates into d_out
    attn_kernel<<<(Nn * 32 + 255) / 256, 256>>>(out, Nn);
}

// round 5
// speedup vs baseline: 1.2747x; 1.2747x over previous
#include <cuda_runtime.h>
#include <cuda_bf16.h>
#include <math_constants.h>

// Problem constants (fixed by the dataset)
#define MAXN 50000
#define MAXE 1600000
#define DIN 128
#define HC 64            // 2 heads * 32 channels
#define SCAN_B 256       // scan block size
#define MAXSB ((MAXN + SCAN_B - 1) / SCAN_B)   // 196

// -------- device scratch (no runtime allocation allowed) --------
__device__ float g_q[MAXN * HC];
__device__ float g_k[MAXN * HC];
__device__ float g_v[MAXN * HC];
__device__ int   g_cnt[MAXN];
__device__ int   g_cur[MAXN];
__device__ int   g_roff[MAXN + 1];
__device__ int   g_src[MAXE];
__device__ int   g_part[MAXSB];

__device__ __forceinline__ float elu1(float x) {
    return x > 0.0f ? x : (__expf(x) - 1.0f);
}

// ============================================================
// Kernel 1: fused ELU + 4 GEMMs (q,k,v,skip).
// Block: 256 threads, tile = 64 nodes x 256 output cols
// (cols = [q(64) | k(64) | v(64) | skip(64)]).
// Static smem: xs[64][128] (32KB) + ws chunk [16][256] (16KB) = 48KB.
// ============================================================
__global__ void __launch_bounds__(256, 1)
gemm_qkvs_kernel(const float* __restrict__ x,
                 const float* __restrict__ Wq, const float* __restrict__ bq,
                 const float* __restrict__ Wk, const float* __restrict__ bk,
                 const float* __restrict__ Wv, const float* __restrict__ bv,
                 const float* __restrict__ Ws, const float* __restrict__ bs,
                 float* __restrict__ oskip, int Nn)
{
    __shared__ __align__(16) float xs[64 * DIN];    // 32 KB
    __shared__ __align__(16) float ws[16 * 256];    // 16 KB
    float4* xs4 = (float4*)xs;
    float4* ws4 = (float4*)ws;

    const int tid = threadIdx.x;
    const int node0 = blockIdx.x * 64;

    // ---- stage x tile with ELU (once) ----
    for (int i = tid; i < (64 * DIN) / 4; i += 256) { // 2048 float4
        int r  = i >> 5;              // 32 float4 per row
        int c4 = i & 31;
        int n  = node0 + r;
        float4 val;
        if (n < Nn) {
            val = ((const float4*)x)[(size_t)n * 32 + c4];
            val.x = elu1(val.x); val.y = elu1(val.y);
            val.z = elu1(val.z); val.w = elu1(val.w);
        } else {
            val = make_float4(0.f, 0.f, 0.f, 0.f);
        }
        xs4[r * 32 + c4] = val;
    }

    // per-thread fixed weight-load assignment
    const int c4   = tid & 63;        // 0..63 across the 256-col tile
    const int lmat = c4 >> 4;         // which matrix this thread loads
    const int lw4  = c4 & 15;         // float4 col within that matrix
    const float4* Wsel4 =
        (const float4*)((lmat == 0) ? Wq : (lmat == 1) ? Wk :
                        (lmat == 2) ? Wv : Ws);

    const int w  = tid >> 5;   // warp 0..7 -> node group
    const int tx = tid & 31;   // lane -> col group
    const int tx2 = tx * 2;    // float4 index into ws row

    float acc[8][8];
    #pragma unroll
    for (int i = 0; i < 8; i++)
        #pragma unroll
        for (int j = 0; j < 8; j++) acc[i][j] = 0.0f;

    for (int d0 = 0; d0 < DIN; d0 += 16) {
        __syncthreads();
        #pragma unroll
        for (int j = 0; j < 4; j++) {
            int dd = (tid >> 6) + 4 * j;         // 0..15
            ws4[dd * 64 + c4] = Wsel4[(d0 + dd) * 16 + lw4];
        }
        __syncthreads();

        #pragma unroll
        for (int dq = 0; dq < 16; dq += 4) {
            float4 xv[8];
            #pragma unroll
            for (int i = 0; i < 8; i++)
                xv[i] = xs4[(w * 8 + i) * 32 + ((d0 + dq) >> 2)];
            #pragma unroll
            for (int dd = 0; dd < 4; dd++) {
                float4 w0 = ws4[(dq + dd) * 64 + tx2];
                float4 w1 = ws4[(dq + dd) * 64 + tx2 + 1];
                #pragma unroll
                for (int i = 0; i < 8; i++) {
                    float xv_s = (dd == 0) ? xv[i].x :
                                 (dd == 1) ? xv[i].y :
                                 (dd == 2) ? xv[i].z : xv[i].w;
                    acc[i][0] = fmaf(xv_s, w0.x, acc[i][0]);
                    acc[i][1] = fmaf(xv_s, w0.y, acc[i][1]);
                    acc[i][2] = fmaf(xv_s, w0.z, acc[i][2]);
                    acc[i][3] = fmaf(xv_s, w0.w, acc[i][3]);
                    acc[i][4] = fmaf(xv_s, w1.x, acc[i][4]);
                    acc[i][5] = fmaf(xv_s, w1.y, acc[i][5]);
                    acc[i][6] = fmaf(xv_s, w1.z, acc[i][6]);
                    acc[i][7] = fmaf(xv_s, w1.w, acc[i][7]);
                }
            }
        }
    }

    // ---- bias + store ----
    const int c0  = tx * 8;
    const int mat = c0 >> 6;     // 0=q,1=k,2=v,3=skip
    const int cm  = c0 & 63;

    const float* bptr;
    float* dptr;
    if      (mat == 0) { bptr = bq; dptr = g_q; }
    else if (mat == 1) { bptr = bk; dptr = g_k; }
    else if (mat == 2) { bptr = bv; dptr = g_v; }
    else               { bptr = bs; dptr = oskip; }

    float4 b0 = ((const float4*)(bptr + cm))[0];
    float4 b1 = ((const float4*)(bptr + cm))[1];

    #pragma unroll
    for (int i = 0; i < 8; i++) {
        int n = node0 + w * 8 + i;
        if (n < Nn) {
            float4 r0 = make_float4(acc[i][0] + b0.x, acc[i][1] + b0.y,
                                    acc[i][2] + b0.z, acc[i][3] + b0.w);
            float4 r1 = make_float4(acc[i][4] + b1.x, acc[i][5] + b1.y,
                                    acc[i][6] + b1.z, acc[i][7] + b1.w);
            float4* dst = (float4*)(dptr + (size_t)n * HC + cm);
            dst[0] = r0;
            dst[1] = r1;
        }
    }
}

// ============================================================
// CSR build (edge_index int32: row 0 = src, row 1 = dst)
// ============================================================
__global__ void zero_counts_kernel(int Nn)
{
    int i = blockIdx.x * blockDim.x + threadIdx.x;
    if (i < Nn) g_cnt[i] = 0;
}

__global__ void hist_kernel(const int* __restrict__ ei, int Ee)
{
    int e = blockIdx.x * blockDim.x + threadIdx.x;
    if (e < Ee) {
        int dst = ei[Ee + e];
        atomicAdd(&g_cnt[dst], 1);
    }
}

// ---- grid-wide exclusive scan, 3 small kernels ----
// warp-scan helper: ALL 32 lanes of the calling warp MUST execute this.
__device__ __forceinline__ int warp_excl_scan(int v, int lane, int* total)
{
    int inc = v;
    #pragma unroll
    for (int off = 1; off < 32; off <<= 1) {
        int t = __shfl_up_sync(0xffffffffu, inc, off);
        if (lane >= off) inc += t;
    }
    *total = __shfl_sync(0xffffffffu, inc, 31);
    return inc - v;
}

// A: per-block reduce of 256 counts -> g_part[b]
__global__ void scan_reduce_kernel(int Nn)
{
    const int i = blockIdx.x * SCAN_B + threadIdx.x;
    int v = (i < Nn) ? g_cnt[i] : 0;
    #pragma unroll
    for (int off = 16; off > 0; off >>= 1)
        v += __shfl_down_sync(0xffffffffu, v, off);
    __shared__ int ws[8];
    const int lane = threadIdx.x & 31, wid = threadIdx.x >> 5;
    if (lane == 0) ws[wid] = v;
    __syncthreads();
    if (wid == 0) {                      // whole warp 0 participates
        int s = (lane < 8) ? ws[lane] : 0;
        #pragma unroll
        for (int off = 4; off > 0; off >>= 1)
            s += __shfl_down_sync(0xffffffffu, s, off);
        if (lane == 0) g_part[blockIdx.x] = s;
    }
}

// B: one block scans the NB (<=256) partials exclusively; writes total
__global__ void scan_partials_kernel(int NB, int Nn)
{
    __shared__ int wtot[8];
    const int t = threadIdx.x, lane = t & 31, wid = t >> 5;
    int v = (t < NB) ? g_part[t] : 0;
    int wt;
    int ex = warp_excl_scan(v, lane, &wt);
    if (lane == 0) wtot[wid] = wt;
    __syncthreads();
    if (wid == 0) {                      // whole warp 0 participates
        int s = (lane < 8) ? wtot[lane] : 0;
        int st;
        int sex = warp_excl_scan(s, lane, &st);
        if (lane < 8) wtot[lane] = sex;
        if (lane == 0) g_roff[Nn] = st;  // grand total = E
    }
    __syncthreads();
    if (t < NB) g_part[t] = ex + wtot[wid];
}

// C: per-block exclusive scan + apply partial offset -> g_roff, g_cur
__global__ void scan_apply_kernel(int Nn)
{
    __shared__ int wtot[8];
    const int i = blockIdx.x * SCAN_B + threadIdx.x;
    const int t = threadIdx.x, lane = t & 31, wid = t >> 5;
    int v = (i < Nn) ? g_cnt[i] : 0;
    int wt;
    int ex = warp_excl_scan(v, lane, &wt);
    if (lane == 0) wtot[wid] = wt;
    __syncthreads();
    if (wid == 0) {                      // whole warp 0 participates
        int s = (lane < 8) ? wtot[lane] : 0;
        int st;
        int sex = warp_excl_scan(s, lane, &st);
        if (lane < 8) wtot[lane] = sex;
    }
    __syncthreads();
    if (i < Nn) {
        int off = g_part[blockIdx.x] + wtot[wid] + ex;
        g_roff[i] = off;
        g_cur[i]  = off;
    }
}

__global__ void scatter_kernel(const int* __restrict__ ei, int Ee)
{
    int e = blockIdx.x * blockDim.x + threadIdx.x;
    if (e < Ee) {
        int src = ei[e];
        int dst = ei[Ee + e];
        int pos = atomicAdd(&g_cur[dst], 1);
        g_src[pos] = src;
    }
}

// ============================================================
// Kernel 3: warp-per-node online-softmax attention, 4-edge unrolled.
// lane l: head h = l>>4, channels c = 2*(l&15) (float2 per lane).
// out[n] += acc/den (out already holds skip GEMM result).
// ============================================================
__device__ __forceinline__ float warp_dot16(float2 qv, float2 kv)
{
    float p = qv.x * kv.x + qv.y * kv.y;
    p += __shfl_xor_sync(0xffffffffu, p, 8);
    p += __shfl_xor_sync(0xffffffffu, p, 4);
    p += __shfl_xor_sync(0xffffffffu, p, 2);
    p += __shfl_xor_sync(0xffffffffu, p, 1);
    return p * 0.17677669529663687f;   // 1/sqrt(32)
}

// online-softmax update; rescale only when max moves.
// branch is uniform within each 16-lane half (alpha identical there).
__device__ __forceinline__ void os_update(float alpha, float2 vv,
                                          float& m, float& den, float2& acc)
{
    if (alpha > m) {
        const float scale = __expf(m - alpha);   // first iter: exp(-inf)=0
        den = den * scale + 1.0f;
        acc.x = acc.x * scale + vv.x;
        acc.y = acc.y * scale + vv.y;
        m = alpha;
    } else {
        const float wgt = __expf(alpha - m);
        den += wgt;
        acc.x += wgt * vv.x;
        acc.y += wgt * vv.y;
    }
}

__global__ void __launch_bounds__(256)
attn_kernel(float* __restrict__ out, int Nn)
{
    const int warp = (blockIdx.x * blockDim.x + threadIdx.x) >> 5;
    if (warp >= Nn) return;
    const int n = warp;
    const int lane = threadIdx.x & 31;
    const int base = (lane >> 4) * 32 + (lane & 15) * 2;   // offset in 64-float row

    const float2 qv = *(const float2*)(g_q + (size_t)n * HC + base);

    float m = -CUDART_INF_F;
    float den = 0.0f;
    float2 acc = make_float2(0.0f, 0.0f);

    const int e0 = g_roff[n];
    const int e1 = g_roff[n + 1];

    int e = e0;
    for (; e + 4 <= e1; e += 4) {
        int s0 = g_src[e + 0];
        int s1 = g_src[e + 1];
        int s2 = g_src[e + 2];
        int s3 = g_src[e + 3];
        const float2 k0 = *(const float2*)(g_k + (size_t)s0 * HC + base);
        const float2 k1 = *(const float2*)(g_k + (size_t)s1 * HC + base);
        const float2 k2 = *(const float2*)(g_k + (size_t)s2 * HC + base);
        const float2 k3 = *(const float2*)(g_k + (size_t)s3 * HC + base);
        const float2 v0 = *(const float2*)(g_v + (size_t)s0 * HC + base);
        const float2 v1 = *(const float2*)(g_v + (size_t)s1 * HC + base);
        const float2 v2 = *(const float2*)(g_v + (size_t)s2 * HC + base);
        const float2 v3 = *(const float2*)(g_v + (size_t)s3 * HC + base);

        const float a0 = warp_dot16(qv, k0);
        const float a1 = warp_dot16(qv, k1);
        const float a2 = warp_dot16(qv, k2);
        const float a3 = warp_dot16(qv, k3);

        os_update(a0, v0, m, den, acc);
        os_update(a1, v1, m, den, acc);
        os_update(a2, v2, m, den, acc);
        os_update(a3, v3, m, den, acc);
    }
    for (; e < e1; e++) {
        int s = g_src[e];
        const float2 kv = *(const float2*)(g_k + (size_t)s * HC + base);
        const float2 vv = *(const float2*)(g_v + (size_t)s * HC + base);
        const float a = warp_dot16(qv, kv);
        os_update(a, vv, m, den, acc);
    }

    if (den > 0.0f) {
        const float inv = 1.0f / den;
        float2* o = (float2*)(out + (size_t)n * HC + base);
        float2 cur = *o;
        cur.x += acc.x * inv;
        cur.y += acc.y * inv;
        *o = cur;
    }
}

// ============================================================
// Launcher — kernel launches ONLY (graph-capture safe).
// ============================================================
extern "C" void kernel_launch(void* const* d_in, const int* in_sizes, int n_in,
                              void* d_out, int out_size)
{
    const float* x   = (const float*)d_in[0];
    const int*   ei  = (const int*)d_in[1];     // int32 (jax x64 disabled)
    const float* Wq  = (const float*)d_in[2];
    const float* bq  = (const float*)d_in[3];
    const float* Wk  = (const float*)d_in[4];
    const float* bk  = (const float*)d_in[5];
    const float* Wv  = (const float*)d_in[6];
    const float* bv  = (const float*)d_in[7];
    const float* Wsk = (const float*)d_in[8];
    const float* bsk = (const float*)d_in[9];
    float* out = (float*)d_out;

    const int Nn = in_sizes[0] / DIN;
    const int Ee = in_sizes[1] / 2;
    const int NB = (Nn + SCAN_B - 1) / SCAN_B;

    // GEMMs: writes g_q, g_k, g_v and the skip term into d_out
    gemm_qkvs_kernel<<<(Nn + 63) / 64, 256>>>(
        x, Wq, bq, Wk, bk, Wv, bv, Wsk, bsk, out, Nn);

    // CSR build by destination node
    zero_counts_kernel<<<(Nn + 255) / 256, 256>>>(Nn);
    hist_kernel<<<(Ee + 255) / 256, 256>>>(ei, Ee);
    scan_reduce_kernel<<<NB, SCAN_B>>>(Nn);
    scan_partials_kernel<<<1, SCAN_B>>>(NB, Nn);
    scan_apply_kernel<<<NB, SCAN_B>>>(Nn);
    scatter_kernel<<<(Ee + 255) / 256, 256>>>(ei, Ee);

    // attention: one warp per destination node, accumulates into d_out
    attn_kernel<<<(Nn * 32 + 255) / 256, 256>>>(out, Nn);
}

// round 6
// speedup vs baseline: 1.2876x; 1.0101x over previous
#include <cuda_runtime.h>
#include <cuda_fp16.h>
#include <math_constants.h>

// Problem constants (fixed by the dataset)
#define MAXN 50000
#define MAXE 1600000
#define DIN 128
#define HC 64            // 2 heads * 32 channels
#define SCAN_B 256       // scan block size
#define MAXSB ((MAXN + SCAN_B - 1) / SCAN_B)   // 196

// -------- device scratch (no runtime allocation allowed) --------
__device__ float  g_q[MAXN * HC];
__device__ __half g_kh[MAXN * HC];
__device__ __half g_vh[MAXN * HC];
__device__ int    g_cnt[MAXN];
__device__ int    g_cur[MAXN];
__device__ int    g_roff[MAXN + 1];
__device__ int    g_src[MAXE];
__device__ int    g_part[MAXSB];

__device__ __forceinline__ float elu1(float x) {
    return x > 0.0f ? x : (__expf(x) - 1.0f);
}

// packed fp32x2 FMA: acc = a*b + acc (element-wise on the two lanes)
#define FFMA2(acc, a, b) \
    asm("fma.rn.f32x2 %0, %1, %2, %0;" : "+l"(acc) : "l"(a), "l"(b))

__device__ __forceinline__ unsigned long long pack2(float lo, float hi) {
    unsigned long long r;
    asm("mov.b64 %0, {%1, %2};" : "=l"(r) : "f"(lo), "f"(hi));
    return r;
}
__device__ __forceinline__ float2 unpack2(unsigned long long p) {
    float lo, hi;
    asm("mov.b64 {%0, %1}, %2;" : "=f"(lo), "=f"(hi) : "l"(p));
    return make_float2(lo, hi);
}

// ============================================================
// Kernel 1: fused ELU + 4 GEMMs (q,k,v,skip) using packed f32x2 FMA.
// Block: 256 threads = 8 warps; tile = 64 nodes x 256 output cols
// (cols = [q(64) | k(64) | v(64) | skip(64)]).
// Warp w owns nodes w*8..w*8+7; lane tx owns cols {tx + 32m : m=0..7}.
// smem: xs[64][128] fp32 (32KB) + wp[8][256] d-pair packed (16KB) = 48KB.
// wp[dp][col] = (W[d0+2dp][col], W[d0+2dp+1][col]) for current 16-d chunk.
// ============================================================
__global__ void __launch_bounds__(256, 1)
gemm_qkvs_kernel(const float* __restrict__ x,
                 const float* __restrict__ Wq, const float* __restrict__ bq,
                 const float* __restrict__ Wk, const float* __restrict__ bk,
                 const float* __restrict__ Wv, const float* __restrict__ bv,
                 const float* __restrict__ Ws, const float* __restrict__ bs,
                 float* __restrict__ oskip, int Nn)
{
    __shared__ __align__(16) float xs[64 * DIN];                   // 32 KB
    __shared__ __align__(16) unsigned long long wp[8 * 256];       // 16 KB

    const int tid = threadIdx.x;
    const int node0 = blockIdx.x * 64;

    // ---- stage x tile with ELU (once) ----
    float4* xs4 = (float4*)xs;
    for (int i = tid; i < (64 * DIN) / 4; i += 256) { // 2048 float4
        int r  = i >> 5;              // 32 float4 per row
        int c4 = i & 31;
        int n  = node0 + r;
        float4 val;
        if (n < Nn) {
            val = ((const float4*)x)[(size_t)n * 32 + c4];
            val.x = elu1(val.x); val.y = elu1(val.y);
            val.z = elu1(val.z); val.w = elu1(val.w);
        } else {
            val = make_float4(0.f, 0.f, 0.f, 0.f);
        }
        xs4[r * 32 + c4] = val;
    }

    // staging identity: this thread stages column `tid` of the 256-col tile
    const int smat = tid >> 6;          // 0..3
    const int scm  = tid & 63;          // col within matrix
    const float* Wstage = (smat == 0) ? Wq : (smat == 1) ? Wk :
                          (smat == 2) ? Wv : Ws;

    const int w  = tid >> 5;   // warp 0..7 -> node group
    const int tx = tid & 31;   // lane -> col set {tx+32m}

    unsigned long long acc2[8][8];      // [node i][col group m], f32x2 partials
    #pragma unroll
    for (int i = 0; i < 8; i++)
        #pragma unroll
        for (int m = 0; m < 8; m++) acc2[i][m] = 0ull;

    for (int d0 = 0; d0 < DIN; d0 += 16) {
        __syncthreads();
        // stage 8 d-pairs for my column
        #pragma unroll
        for (int dp = 0; dp < 8; dp++) {
            float lo = Wstage[(d0 + 2 * dp)     * 64 + scm];
            float hi = Wstage[(d0 + 2 * dp + 1) * 64 + scm];
            wp[dp * 256 + tid] = pack2(lo, hi);
        }
        __syncthreads();

        #pragma unroll
        for (int dp = 0; dp < 8; dp++) {
            unsigned long long xv[8];
            #pragma unroll
            for (int i = 0; i < 8; i++)
                xv[i] = *(const unsigned long long*)
                        &xs[(w * 8 + i) * DIN + d0 + 2 * dp];   // broadcast
            unsigned long long wv[8];
            #pragma unroll
            for (int m = 0; m < 8; m++)
                wv[m] = wp[dp * 256 + tx + 32 * m];
            #pragma unroll
            for (int i = 0; i < 8; i++)
                #pragma unroll
                for (int m = 0; m < 8; m++)
                    FFMA2(acc2[i][m], xv[i], wv[m]);
        }
    }

    // ---- reduce pairs, add bias, store ----
    // col = tx + 32m; mat = m>>1; cm = tx + 32*(m&1)
    float bias[8];
    #pragma unroll
    for (int m = 0; m < 8; m++) {
        const int cm = tx + 32 * (m & 1);
        const float* bptr = ((m >> 1) == 0) ? bq : ((m >> 1) == 1) ? bk :
                            ((m >> 1) == 2) ? bv : bs;
        bias[m] = bptr[cm];
    }

    #pragma unroll
    for (int i = 0; i < 8; i++) {
        const int n = node0 + w * 8 + i;
        if (n >= Nn) break;
        #pragma unroll
        for (int m = 0; m < 8; m++) {
            float2 p = unpack2(acc2[i][m]);
            float r = p.x + p.y + bias[m];
            const int cm = tx + 32 * (m & 1);
            const int mat = m >> 1;
            if      (mat == 0) g_q  [(size_t)n * HC + cm] = r;
            else if (mat == 1) g_kh [(size_t)n * HC + cm] = __float2half_rn(r);
            else if (mat == 2) g_vh [(size_t)n * HC + cm] = __float2half_rn(r);
            else               oskip[(size_t)n * HC + cm] = r;
        }
    }
}

// ============================================================
// CSR build (edge_index int32: row 0 = src, row 1 = dst)
// ============================================================
__global__ void zero_counts_kernel(int Nn)
{
    int i = blockIdx.x * blockDim.x + threadIdx.x;
    if (i < Nn) g_cnt[i] = 0;
}

__global__ void hist_kernel(const int* __restrict__ ei, int Ee)
{
    int e = blockIdx.x * blockDim.x + threadIdx.x;
    if (e < Ee) {
        int dst = ei[Ee + e];
        atomicAdd(&g_cnt[dst], 1);
    }
}

// ---- grid-wide exclusive scan, 3 small kernels ----
// warp-scan helper: ALL 32 lanes of the calling warp MUST execute this.
__device__ __forceinline__ int warp_excl_scan(int v, int lane, int* total)
{
    int inc = v;
    #pragma unroll
    for (int off = 1; off < 32; off <<= 1) {
        int t = __shfl_up_sync(0xffffffffu, inc, off);
        if (lane >= off) inc += t;
    }
    *total = __shfl_sync(0xffffffffu, inc, 31);
    return inc - v;
}

// A: per-block reduce of 256 counts -> g_part[b]
__global__ void scan_reduce_kernel(int Nn)
{
    const int i = blockIdx.x * SCAN_B + threadIdx.x;
    int v = (i < Nn) ? g_cnt[i] : 0;
    #pragma unroll
    for (int off = 16; off > 0; off >>= 1)
        v += __shfl_down_sync(0xffffffffu, v, off);
    __shared__ int ws[8];
    const int lane = threadIdx.x & 31, wid = threadIdx.x >> 5;
    if (lane == 0) ws[wid] = v;
    __syncthreads();
    if (wid == 0) {                      // whole warp 0 participates
        int s = (lane < 8) ? ws[lane] : 0;
        #pragma unroll
        for (int off = 4; off > 0; off >>= 1)
            s += __shfl_down_sync(0xffffffffu, s, off);
        if (lane == 0) g_part[blockIdx.x] = s;
    }
}

// B: one block scans the NB (<=256) partials exclusively; writes total
__global__ void scan_partials_kernel(int NB, int Nn)
{
    __shared__ int wtot[8];
    const int t = threadIdx.x, lane = t & 31, wid = t >> 5;
    int v = (t < NB) ? g_part[t] : 0;
    int wt;
    int ex = warp_excl_scan(v, lane, &wt);
    if (lane == 0) wtot[wid] = wt;
    __syncthreads();
    if (wid == 0) {                      // whole warp 0 participates
        int s = (lane < 8) ? wtot[lane] : 0;
        int st;
        int sex = warp_excl_scan(s, lane, &st);
        if (lane < 8) wtot[lane] = sex;
        if (lane == 0) g_roff[Nn] = st;  // grand total = E
    }
    __syncthreads();
    if (t < NB) g_part[t] = ex + wtot[wid];
}

// C: per-block exclusive scan + apply partial offset -> g_roff, g_cur
__global__ void scan_apply_kernel(int Nn)
{
    __shared__ int wtot[8];
    const int i = blockIdx.x * SCAN_B + threadIdx.x;
    const int t = threadIdx.x, lane = t & 31, wid = t >> 5;
    int v = (i < Nn) ? g_cnt[i] : 0;
    int wt;
    int ex = warp_excl_scan(v, lane, &wt);
    if (lane == 0) wtot[wid] = wt;
    __syncthreads();
    if (wid == 0) {                      // whole warp 0 participates
        int s = (lane < 8) ? wtot[lane] : 0;
        int st;
        int sex = warp_excl_scan(s, lane, &st);
        if (lane < 8) wtot[lane] = sex;
    }
    __syncthreads();
    if (i < Nn) {
        int off = g_part[blockIdx.x] + wtot[wid] + ex;
        g_roff[i] = off;
        g_cur[i]  = off;
    }
}

__global__ void scatter_kernel(const int* __restrict__ ei, int Ee)
{
    int e = blockIdx.x * blockDim.x + threadIdx.x;
    if (e < Ee) {
        int src = ei[e];
        int dst = ei[Ee + e];
        int pos = atomicAdd(&g_cur[dst], 1);
        g_src[pos] = src;
    }
}

// ============================================================
// Kernel 3: warp-per-node online-softmax attention, 4-edge unrolled.
// k,v are fp16 (half the L2 traffic). lane l: head h = l>>4,
// channels 2*(l&15), 2*(l&15)+1 (half2 per lane per row).
// out[n] += acc/den (out already holds skip GEMM result).
// ============================================================
__device__ __forceinline__ float warp_dot16(float2 qv, float2 kv)
{
    float p = qv.x * kv.x + qv.y * kv.y;
    p += __shfl_xor_sync(0xffffffffu, p, 8);
    p += __shfl_xor_sync(0xffffffffu, p, 4);
    p += __shfl_xor_sync(0xffffffffu, p, 2);
    p += __shfl_xor_sync(0xffffffffu, p, 1);
    return p * 0.17677669529663687f;   // 1/sqrt(32)
}

// online-softmax update; rescale only when max moves.
// branch is uniform within each 16-lane half (alpha identical there).
__device__ __forceinline__ void os_update(float alpha, float2 vv,
                                          float& m, float& den, float2& acc)
{
    if (alpha > m) {
        const float scale = __expf(m - alpha);   // first iter: exp(-inf)=0
        den = den * scale + 1.0f;
        acc.x = acc.x * scale + vv.x;
        acc.y = acc.y * scale + vv.y;
        m = alpha;
    } else {
        const float wgt = __expf(alpha - m);
        den += wgt;
        acc.x += wgt * vv.x;
        acc.y += wgt * vv.y;
    }
}

__global__ void __launch_bounds__(256)
attn_kernel(float* __restrict__ out, int Nn)
{
    const int warp = (blockIdx.x * blockDim.x + threadIdx.x) >> 5;
    if (warp >= Nn) return;
    const int n = warp;
    const int lane = threadIdx.x & 31;
    const int base = (lane >> 4) * 32 + (lane & 15) * 2;   // offset in 64-elem row

    const float2 qv = *(const float2*)(g_q + (size_t)n * HC + base);

    float m = -CUDART_INF_F;
    float den = 0.0f;
    float2 acc = make_float2(0.0f, 0.0f);

    const int e0 = g_roff[n];
    const int e1 = g_roff[n + 1];

    int e = e0;
    for (; e + 4 <= e1; e += 4) {
        int s0 = g_src[e + 0];
        int s1 = g_src[e + 1];
        int s2 = g_src[e + 2];
        int s3 = g_src[e + 3];
        const float2 k0 = __half22float2(*(const __half2*)(g_kh + (size_t)s0 * HC + base));
        const float2 k1 = __half22float2(*(const __half2*)(g_kh + (size_t)s1 * HC + base));
        const float2 k2 = __half22float2(*(const __half2*)(g_kh + (size_t)s2 * HC + base));
        const float2 k3 = __half22float2(*(const __half2*)(g_kh + (size_t)s3 * HC + base));
        const float2 v0 = __half22float2(*(const __half2*)(g_vh + (size_t)s0 * HC + base));
        const float2 v1 = __half22float2(*(const __half2*)(g_vh + (size_t)s1 * HC + base));
        const float2 v2 = __half22float2(*(const __half2*)(g_vh + (size_t)s2 * HC + base));
        const float2 v3 = __half22float2(*(const __half2*)(g_vh + (size_t)s3 * HC + base));

        const float a0 = warp_dot16(qv, k0);
        const float a1 = warp_dot16(qv, k1);
        const float a2 = warp_dot16(qv, k2);
        const float a3 = warp_dot16(qv, k3);

        os_update(a0, v0, m, den, acc);
        os_update(a1, v1, m, den, acc);
        os_update(a2, v2, m, den, acc);
        os_update(a3, v3, m, den, acc);
    }
    for (; e < e1; e++) {
        int s = g_src[e];
        const float2 kv = __half22float2(*(const __half2*)(g_kh + (size_t)s * HC + base));
        const float2 vv = __half22float2(*(const __half2*)(g_vh + (size_t)s * HC + base));
        const float a = warp_dot16(qv, kv);
        os_update(a, vv, m, den, acc);
    }

    if (den > 0.0f) {
        const float inv = 1.0f / den;
        float2* o = (float2*)(out + (size_t)n * HC + base);
        float2 cur = *o;
        cur.x += acc.x * inv;
        cur.y += acc.y * inv;
        *o = cur;
    }
}

// ============================================================
// Launcher — kernel launches ONLY (graph-capture safe).
// ============================================================
extern "C" void kernel_launch(void* const* d_in, const int* in_sizes, int n_in,
                              void* d_out, int out_size)
{
    const float* x   = (const float*)d_in[0];
    const int*   ei  = (const int*)d_in[1];     // int32 (jax x64 disabled)
    const float* Wq  = (const float*)d_in[2];
    const float* bq  = (const float*)d_in[3];
    const float* Wk  = (const float*)d_in[4];
    const float* bk  = (const float*)d_in[5];
    const float* Wv  = (const float*)d_in[6];
    const float* bv  = (const float*)d_in[7];
    const float* Wsk = (const float*)d_in[8];
    const float* bsk = (const float*)d_in[9];
    float* out = (float*)d_out;

    const int Nn = in_sizes[0] / DIN;
    const int Ee = in_sizes[1] / 2;
    const int NB = (Nn + SCAN_B - 1) / SCAN_B;

    // GEMMs: writes g_q, g_kh, g_vh and the skip term into d_out
    gemm_qkvs_kernel<<<(Nn + 63) / 64, 256>>>(
        x, Wq, bq, Wk, bk, Wv, bv, Wsk, bsk, out, Nn);

    // CSR build by destination node
    zero_counts_kernel<<<(Nn + 255) / 256, 256>>>(Nn);
    hist_kernel<<<(Ee + 255) / 256, 256>>>(ei, Ee);
    scan_reduce_kernel<<<NB, SCAN_B>>>(Nn);
    scan_partials_kernel<<<1, SCAN_B>>>(NB, Nn);
    scan_apply_kernel<<<NB, SCAN_B>>>(Nn);
    scatter_kernel<<<(Ee + 255) / 256, 256>>>(ei, Ee);

    // attention: one warp per destination node, accumulates into d_out
    attn_kernel<<<(Nn * 32 + 255) / 256, 256>>>(out, Nn);
}

// round 7
// speedup vs baseline: 1.2960x; 1.0065x over previous
#include <cuda_runtime.h>
#include <cuda_fp16.h>
#include <math_constants.h>

// Problem constants (fixed by the dataset)
#define MAXN 50000
#define MAXE 1600000
#define DIN 128
#define HC 64            // 2 heads * 32 channels
#define SCAN_B 256       // scan block size
#define MAXSB ((MAXN + SCAN_B - 1) / SCAN_B)   // 196

// -------- device scratch (no runtime allocation allowed) --------
__device__ float  g_q[MAXN * HC];
__device__ __half g_kh[MAXN * HC];
__device__ __half g_vh[MAXN * HC];
__device__ int    g_cnt[MAXN];          // zero-initialized at module load
__device__ int    g_cur[MAXN];
__device__ int    g_roff[MAXN + 1];
__device__ int    g_src[MAXE];
__device__ int    g_part[MAXSB];

__device__ __forceinline__ float elu1(float x) {
    return x > 0.0f ? x : (__expf(x) - 1.0f);
}

// packed fp32x2 FMA: acc = a*b + acc (element-wise on the two lanes)
#define FFMA2(acc, a, b) \
    asm("fma.rn.f32x2 %0, %1, %2, %0;" : "+l"(acc) : "l"(a), "l"(b))

__device__ __forceinline__ unsigned long long pack2(float lo, float hi) {
    unsigned long long r;
    asm("mov.b64 %0, {%1, %2};" : "=l"(r) : "f"(lo), "f"(hi));
    return r;
}
__device__ __forceinline__ float2 unpack2(unsigned long long p) {
    float lo, hi;
    asm("mov.b64 {%0, %1}, %2;" : "=f"(lo), "=f"(hi) : "l"(p));
    return make_float2(lo, hi);
}

// ============================================================
// Kernel: fused ELU + 4 GEMMs (q,k,v,skip) using packed f32x2 FMA.
// Block: 256 threads = 8 warps; tile = 64 nodes x 256 output cols.
// ============================================================
__global__ void __launch_bounds__(256, 1)
gemm_qkvs_kernel(const float* __restrict__ x,
                 const float* __restrict__ Wq, const float* __restrict__ bq,
                 const float* __restrict__ Wk, const float* __restrict__ bk,
                 const float* __restrict__ Wv, const float* __restrict__ bv,
                 const float* __restrict__ Ws, const float* __restrict__ bs,
                 float* __restrict__ oskip, int Nn)
{
    __shared__ __align__(16) float xs[64 * DIN];                   // 32 KB
    __shared__ __align__(16) unsigned long long wp[8 * 256];       // 16 KB

    const int tid = threadIdx.x;
    const int node0 = blockIdx.x * 64;

    // ---- stage x tile with ELU (once) ----
    float4* xs4 = (float4*)xs;
    for (int i = tid; i < (64 * DIN) / 4; i += 256) { // 2048 float4
        int r  = i >> 5;              // 32 float4 per row
        int c4 = i & 31;
        int n  = node0 + r;
        float4 val;
        if (n < Nn) {
            val = ((const float4*)x)[(size_t)n * 32 + c4];
            val.x = elu1(val.x); val.y = elu1(val.y);
            val.z = elu1(val.z); val.w = elu1(val.w);
        } else {
            val = make_float4(0.f, 0.f, 0.f, 0.f);
        }
        xs4[r * 32 + c4] = val;
    }

    // staging identity: this thread stages column `tid` of the 256-col tile
    const int smat = tid >> 6;          // 0..3
    const int scm  = tid & 63;          // col within matrix
    const float* Wstage = (smat == 0) ? Wq : (smat == 1) ? Wk :
                          (smat == 2) ? Wv : Ws;

    const int w  = tid >> 5;   // warp 0..7 -> node group
    const int tx = tid & 31;   // lane -> col set {tx+32m}

    unsigned long long acc2[8][8];      // [node i][col group m], f32x2 partials
    #pragma unroll
    for (int i = 0; i < 8; i++)
        #pragma unroll
        for (int m = 0; m < 8; m++) acc2[i][m] = 0ull;

    for (int d0 = 0; d0 < DIN; d0 += 16) {
        __syncthreads();
        // stage 8 d-pairs for my column
        #pragma unroll
        for (int dp = 0; dp < 8; dp++) {
            float lo = Wstage[(d0 + 2 * dp)     * 64 + scm];
            float hi = Wstage[(d0 + 2 * dp + 1) * 64 + scm];
            wp[dp * 256 + tid] = pack2(lo, hi);
        }
        __syncthreads();

        #pragma unroll
        for (int dp = 0; dp < 8; dp++) {
            unsigned long long xv[8];
            #pragma unroll
            for (int i = 0; i < 8; i++)
                xv[i] = *(const unsigned long long*)
                        &xs[(w * 8 + i) * DIN + d0 + 2 * dp];   // broadcast
            unsigned long long wv[8];
            #pragma unroll
            for (int m = 0; m < 8; m++)
                wv[m] = wp[dp * 256 + tx + 32 * m];
            #pragma unroll
            for (int i = 0; i < 8; i++)
                #pragma unroll
                for (int m = 0; m < 8; m++)
                    FFMA2(acc2[i][m], xv[i], wv[m]);
        }
    }

    // ---- reduce pairs, add bias, store ----
    float bias[8];
    #pragma unroll
    for (int m = 0; m < 8; m++) {
        const int cm = tx + 32 * (m & 1);
        const float* bptr = ((m >> 1) == 0) ? bq : ((m >> 1) == 1) ? bk :
                            ((m >> 1) == 2) ? bv : bs;
        bias[m] = bptr[cm];
    }

    #pragma unroll
    for (int i = 0; i < 8; i++) {
        const int n = node0 + w * 8 + i;
        if (n >= Nn) break;
        #pragma unroll
        for (int m = 0; m < 8; m++) {
            float2 p = unpack2(acc2[i][m]);
            float r = p.x + p.y + bias[m];
            const int cm = tx + 32 * (m & 1);
            const int mat = m >> 1;
            if      (mat == 0) g_q  [(size_t)n * HC + cm] = r;
            else if (mat == 1) g_kh [(size_t)n * HC + cm] = __float2half_rn(r);
            else if (mat == 2) g_vh [(size_t)n * HC + cm] = __float2half_rn(r);
            else               oskip[(size_t)n * HC + cm] = r;
        }
    }
}

// ============================================================
// CSR build (edge_index int32: row 0 = src, row 1 = dst)
// g_cnt is zeroed by scan_apply at the end of each call, so it is
// zero on entry to hist (zero-init at load; restored every call).
// ============================================================
__global__ void hist_kernel(const int* __restrict__ ei, int Ee)
{
    int e = blockIdx.x * blockDim.x + threadIdx.x;
    if (e < Ee) {
        int dst = ei[Ee + e];
        atomicAdd(&g_cnt[dst], 1);
    }
}

// warp-scan helper: ALL 32 lanes of the calling warp MUST execute this.
__device__ __forceinline__ int warp_excl_scan(int v, int lane, int* total)
{
    int inc = v;
    #pragma unroll
    for (int off = 1; off < 32; off <<= 1) {
        int t = __shfl_up_sync(0xffffffffu, inc, off);
        if (lane >= off) inc += t;
    }
    *total = __shfl_sync(0xffffffffu, inc, 31);
    return inc - v;
}

// A: per-block reduce of 256 counts -> g_part[b]
__global__ void scan_reduce_kernel(int Nn)
{
    const int i = blockIdx.x * SCAN_B + threadIdx.x;
    int v = (i < Nn) ? g_cnt[i] : 0;
    #pragma unroll
    for (int off = 16; off > 0; off >>= 1)
        v += __shfl_down_sync(0xffffffffu, v, off);
    __shared__ int ws[8];
    const int lane = threadIdx.x & 31, wid = threadIdx.x >> 5;
    if (lane == 0) ws[wid] = v;
    __syncthreads();
    if (wid == 0) {                      // whole warp 0 participates
        int s = (lane < 8) ? ws[lane] : 0;
        #pragma unroll
        for (int off = 4; off > 0; off >>= 1)
            s += __shfl_down_sync(0xffffffffu, s, off);
        if (lane == 0) g_part[blockIdx.x] = s;
    }
}

// B: per-block: redundantly scan partials in smem, then exclusive-scan
// own 256-count chunk, write g_roff/g_cur, zero g_cnt, set g_roff[Nn].
__global__ void scan_apply_kernel(int NB, int Nn)
{
    __shared__ int pex[SCAN_B];   // exclusive scan of partials
    __shared__ int wtot[8];
    const int t = threadIdx.x, lane = t & 31, wid = t >> 5;

    // --- scan the NB partials (all blocks redundantly) ---
    {
        int v = (t < NB) ? g_part[t] : 0;
        int wt;
        int ex = warp_excl_scan(v, lane, &wt);
        if (lane == 0) wtot[wid] = wt;
        __syncthreads();
        if (wid == 0) {
            int s = (lane < 8) ? wtot[lane] : 0;
            int st;
            int sex = warp_excl_scan(s, lane, &st);
            if (lane < 8) wtot[lane] = sex;
            if (lane == 0 && blockIdx.x == 0) g_roff[Nn] = st;  // total = E
        }
        __syncthreads();
        pex[t] = ex + wtot[wid];
        __syncthreads();
    }
    const int base = pex[blockIdx.x];
    __syncthreads();   // wtot reused below

    // --- scan own chunk ---
    const int i = blockIdx.x * SCAN_B + t;
    int v = (i < Nn) ? g_cnt[i] : 0;
    int wt;
    int ex = warp_excl_scan(v, lane, &wt);
    if (lane == 0) wtot[wid] = wt;
    __syncthreads();
    if (wid == 0) {
        int s = (lane < 8) ? wtot[lane] : 0;
        int st;
        int sex = warp_excl_scan(s, lane, &st);
        if (lane < 8) wtot[lane] = sex;
    }
    __syncthreads();
    if (i < Nn) {
        int off = base + wtot[wid] + ex;
        g_roff[i] = off;
        g_cur[i]  = off;
        g_cnt[i]  = 0;          // reset for next call (graph replay safe)
    }
}

__global__ void scatter_kernel(const int* __restrict__ ei, int Ee)
{
    int e = blockIdx.x * blockDim.x + threadIdx.x;
    if (e < Ee) {
        int src = ei[e];
        int dst = ei[Ee + e];
        int pos = atomicAdd(&g_cur[dst], 1);
        g_src[pos] = src;
    }
}

// ============================================================
// Attention: warp-per-node online softmax, 4-edge groups with
// src-prefetch software pipeline. k,v fp16.
// ============================================================
__device__ __forceinline__ float warp_dot16(float2 qv, float2 kv)
{
    float p = qv.x * kv.x + qv.y * kv.y;
    p += __shfl_xor_sync(0xffffffffu, p, 8);
    p += __shfl_xor_sync(0xffffffffu, p, 4);
    p += __shfl_xor_sync(0xffffffffu, p, 2);
    p += __shfl_xor_sync(0xffffffffu, p, 1);
    return p * 0.17677669529663687f;   // 1/sqrt(32)
}

__device__ __forceinline__ void os_update(float alpha, float2 vv,
                                          float& m, float& den, float2& acc)
{
    if (alpha > m) {
        const float scale = __expf(m - alpha);   // first iter: exp(-inf)=0
        den = den * scale + 1.0f;
        acc.x = acc.x * scale + vv.x;
        acc.y = acc.y * scale + vv.y;
        m = alpha;
    } else {
        const float wgt = __expf(alpha - m);
        den += wgt;
        acc.x += wgt * vv.x;
        acc.y += wgt * vv.y;
    }
}

__global__ void __launch_bounds__(256)
attn_kernel(float* __restrict__ out, int Nn)
{
    const int warp = (blockIdx.x * blockDim.x + threadIdx.x) >> 5;
    if (warp >= Nn) return;
    const int n = warp;
    const int lane = threadIdx.x & 31;
    const int base = (lane >> 4) * 32 + (lane & 15) * 2;   // offset in 64-elem row

    const float2 qv = *(const float2*)(g_q + n * HC + base);

    float m = -CUDART_INF_F;
    float den = 0.0f;
    float2 acc = make_float2(0.0f, 0.0f);

    const int e0 = g_roff[n];
    const int e1 = g_roff[n + 1];

    int e = e0;
    if (e + 4 <= e1) {
        // prologue: load first group's src
        int s0 = g_src[e + 0];
        int s1 = g_src[e + 1];
        int s2 = g_src[e + 2];
        int s3 = g_src[e + 3];
        for (;;) {
            const bool more = (e + 8 <= e1);
            int t0, t1, t2, t3;
            if (more) {                  // prefetch next group's src
                t0 = g_src[e + 4];
                t1 = g_src[e + 5];
                t2 = g_src[e + 6];
                t3 = g_src[e + 7];
            }
            const int r0 = s0 << 6, r1 = s1 << 6, r2 = s2 << 6, r3 = s3 << 6;
            const float2 k0 = __half22float2(*(const __half2*)(g_kh + r0 + base));
            const float2 k1 = __half22float2(*(const __half2*)(g_kh + r1 + base));
            const float2 k2 = __half22float2(*(const __half2*)(g_kh + r2 + base));
            const float2 k3 = __half22float2(*(const __half2*)(g_kh + r3 + base));
            const float2 v0 = __half22float2(*(const __half2*)(g_vh + r0 + base));
            const float2 v1 = __half22float2(*(const __half2*)(g_vh + r1 + base));
            const float2 v2 = __half22float2(*(const __half2*)(g_vh + r2 + base));
            const float2 v3 = __half22float2(*(const __half2*)(g_vh + r3 + base));

            const float a0 = warp_dot16(qv, k0);
            const float a1 = warp_dot16(qv, k1);
            const float a2 = warp_dot16(qv, k2);
            const float a3 = warp_dot16(qv, k3);

            os_update(a0, v0, m, den, acc);
            os_update(a1, v1, m, den, acc);
            os_update(a2, v2, m, den, acc);
            os_update(a3, v3, m, den, acc);

            e += 4;
            if (!more) break;
            s0 = t0; s1 = t1; s2 = t2; s3 = t3;
        }
    }
    for (; e < e1; e++) {
        const int r = g_src[e] << 6;
        const float2 kv = __half22float2(*(const __half2*)(g_kh + r + base));
        const float2 vv = __half22float2(*(const __half2*)(g_vh + r + base));
        const float a = warp_dot16(qv, kv);
        os_update(a, vv, m, den, acc);
    }

    if (den > 0.0f) {
        const float inv = 1.0f / den;
        float2* o = (float2*)(out + n * HC + base);
        float2 cur = *o;
        cur.x += acc.x * inv;
        cur.y += acc.y * inv;
        *o = cur;
    }
}

// ============================================================
// Launcher — kernel launches ONLY (graph-capture safe).
// Order chosen so gemm is launch index 3 (the profiled slot).
// ============================================================
extern "C" void kernel_launch(void* const* d_in, const int* in_sizes, int n_in,
                              void* d_out, int out_size)
{
    const float* x   = (const float*)d_in[0];
    const int*   ei  = (const int*)d_in[1];     // int32 (jax x64 disabled)
    const float* Wq  = (const float*)d_in[2];
    const float* bq  = (const float*)d_in[3];
    const float* Wk  = (const float*)d_in[4];
    const float* bk  = (const float*)d_in[5];
    const float* Wv  = (const float*)d_in[6];
    const float* bv  = (const float*)d_in[7];
    const float* Wsk = (const float*)d_in[8];
    const float* bsk = (const float*)d_in[9];
    float* out = (float*)d_out;

    const int Nn = in_sizes[0] / DIN;
    const int Ee = in_sizes[1] / 2;
    const int NB = (Nn + SCAN_B - 1) / SCAN_B;

    // CSR build by destination node (g_cnt zeroed by previous call's apply)
    hist_kernel<<<(Ee + 255) / 256, 256>>>(ei, Ee);               // 0
    scan_reduce_kernel<<<NB, SCAN_B>>>(Nn);                        // 1
    scan_apply_kernel<<<NB, SCAN_B>>>(NB, Nn);                     // 2

    // GEMMs (independent of CSR): g_q, g_kh, g_vh, skip -> d_out   // 3 (profiled)
    gemm_qkvs_kernel<<<(Nn + 63) / 64, 256>>>(
        x, Wq, bq, Wk, bk, Wv, bv, Wsk, bsk, out, Nn);

    scatter_kernel<<<(Ee + 255) / 256, 256>>>(ei, Ee);             // 4

    // attention: one warp per destination node, accumulates into d_out
    attn_kernel<<<(Nn * 32 + 255) / 256, 256>>>(out, Nn);          // 5
}

// round 8
// speedup vs baseline: 1.3876x; 1.0707x over previous
#include <cuda_runtime.h>
#include <cuda_fp16.h>
#include <math_constants.h>

// Problem constants (fixed by the dataset)
#define MAXN 50000
#define MAXE 1600000
#define DIN 128
#define HC 64            // 2 heads * 32 channels
#define SCAN_B 256       // scan block size
#define MAXSB ((MAXN + SCAN_B - 1) / SCAN_B)   // 196

// -------- device scratch (no runtime allocation allowed) --------
__device__ float  g_q[MAXN * HC];
__device__ __half g_kh[MAXN * HC];
__device__ __half g_vh[MAXN * HC];
__device__ int    g_cnt[MAXN];          // zero-initialized at module load
__device__ int    g_cur[MAXN];
__device__ int    g_roff[MAXN + 1];
__device__ int    g_src[MAXE];
__device__ int    g_part[MAXSB];

__device__ __forceinline__ float elu1(float x) {
    return x > 0.0f ? x : (__expf(x) - 1.0f);
}

// packed fp32x2 FMA: acc = a*b + acc (element-wise on the two lanes)
#define FFMA2(acc, a, b) \
    asm("fma.rn.f32x2 %0, %1, %2, %0;" : "+l"(acc) : "l"(a), "l"(b))

__device__ __forceinline__ unsigned long long pack2(float lo, float hi) {
    unsigned long long r;
    asm("mov.b64 %0, {%1, %2};" : "=l"(r) : "f"(lo), "f"(hi));
    return r;
}
__device__ __forceinline__ float2 unpack2(unsigned long long p) {
    float lo, hi;
    asm("mov.b64 {%0, %1}, %2;" : "=f"(lo), "=f"(hi) : "l"(p));
    return make_float2(lo, hi);
}

// ============================================================
// Kernel: fused ELU + 4 GEMMs (q,k,v,skip), packed f32x2 FMA.
// Tile: 32 nodes x 256 cols per 256-thread block (2 CTAs/SM target).
// Warp w (0..7) owns nodes w*4..w*4+3; lane tx owns cols {tx+32m}.
// smem: xs[32][128] fp32 (16KB) + wp[8][256] u64 d-pairs (16KB) = 32KB.
// ============================================================
__global__ void __launch_bounds__(256, 2)
gemm_qkvs_kernel(const float* __restrict__ x,
                 const float* __restrict__ Wq, const float* __restrict__ bq,
                 const float* __restrict__ Wk, const float* __restrict__ bk,
                 const float* __restrict__ Wv, const float* __restrict__ bv,
                 const float* __restrict__ Ws, const float* __restrict__ bs,
                 float* __restrict__ oskip, int Nn)
{
    __shared__ __align__(16) float xs[32 * DIN];                   // 16 KB
    __shared__ __align__(16) unsigned long long wp[8 * 256];       // 16 KB

    const int tid = threadIdx.x;
    const int node0 = blockIdx.x * 32;

    // ---- stage x tile with ELU (once): 1024 float4, 4 per thread ----
    float4* xs4 = (float4*)xs;
    #pragma unroll
    for (int j = 0; j < 4; j++) {
        int i = tid + j * 256;
        int r  = i >> 5;              // 32 float4 per row
        int c4 = i & 31;
        int n  = node0 + r;
        float4 val;
        if (n < Nn) {
            val = ((const float4*)x)[(size_t)n * 32 + c4];
            val.x = elu1(val.x); val.y = elu1(val.y);
            val.z = elu1(val.z); val.w = elu1(val.w);
        } else {
            val = make_float4(0.f, 0.f, 0.f, 0.f);
        }
        xs4[r * 32 + c4] = val;
    }

    // staging identity: this thread stages column `tid` of the 256-col tile
    const int smat = tid >> 6;          // 0..3
    const int scm  = tid & 63;          // col within matrix
    const float* Wstage = (smat == 0) ? Wq : (smat == 1) ? Wk :
                          (smat == 2) ? Wv : Ws;

    const int w  = tid >> 5;   // warp 0..7 -> 4-node group
    const int tx = tid & 31;   // lane -> col set {tx+32m}

    unsigned long long acc2[4][8];      // [node i][col group m], f32x2 partials
    #pragma unroll
    for (int i = 0; i < 4; i++)
        #pragma unroll
        for (int m = 0; m < 8; m++) acc2[i][m] = 0ull;

    for (int d0 = 0; d0 < DIN; d0 += 16) {
        __syncthreads();
        // stage 8 d-pairs for my column
        #pragma unroll
        for (int dp = 0; dp < 8; dp++) {
            float lo = Wstage[(d0 + 2 * dp)     * 64 + scm];
            float hi = Wstage[(d0 + 2 * dp + 1) * 64 + scm];
            wp[dp * 256 + tid] = pack2(lo, hi);
        }
        __syncthreads();

        #pragma unroll
        for (int dp = 0; dp < 8; dp++) {
            unsigned long long xv[4];
            #pragma unroll
            for (int i = 0; i < 4; i++)
                xv[i] = *(const unsigned long long*)
                        &xs[(w * 4 + i) * DIN + d0 + 2 * dp];   // broadcast
            unsigned long long wv[8];
            #pragma unroll
            for (int m = 0; m < 8; m++)
                wv[m] = wp[dp * 256 + tx + 32 * m];
            #pragma unroll
            for (int i = 0; i < 4; i++)
                #pragma unroll
                for (int m = 0; m < 8; m++)
                    FFMA2(acc2[i][m], xv[i], wv[m]);
        }
    }

    // ---- reduce pairs, add bias, store ----
    float bias[8];
    #pragma unroll
    for (int m = 0; m < 8; m++) {
        const int cm = tx + 32 * (m & 1);
        const float* bptr = ((m >> 1) == 0) ? bq : ((m >> 1) == 1) ? bk :
                            ((m >> 1) == 2) ? bv : bs;
        bias[m] = bptr[cm];
    }

    #pragma unroll
    for (int i = 0; i < 4; i++) {
        const int n = node0 + w * 4 + i;
        if (n >= Nn) break;
        #pragma unroll
        for (int m = 0; m < 8; m++) {
            float2 p = unpack2(acc2[i][m]);
            float r = p.x + p.y + bias[m];
            const int cm = tx + 32 * (m & 1);
            const int mat = m >> 1;
            if      (mat == 0) g_q  [(size_t)n * HC + cm] = r;
            else if (mat == 1) g_kh [(size_t)n * HC + cm] = __float2half_rn(r);
            else if (mat == 2) g_vh [(size_t)n * HC + cm] = __float2half_rn(r);
            else               oskip[(size_t)n * HC + cm] = r;
        }
    }
}

// ============================================================
// CSR build (edge_index int32: row 0 = src, row 1 = dst)
// g_cnt zeroed at load and re-zeroed by scan_apply each call.
// ============================================================
__global__ void hist_kernel(const int* __restrict__ ei, int Ee)
{
    int e = blockIdx.x * blockDim.x + threadIdx.x;
    if (e < Ee) {
        int dst = ei[Ee + e];
        atomicAdd(&g_cnt[dst], 1);
    }
}

// warp-scan helper: ALL 32 lanes of the calling warp MUST execute this.
__device__ __forceinline__ int warp_excl_scan(int v, int lane, int* total)
{
    int inc = v;
    #pragma unroll
    for (int off = 1; off < 32; off <<= 1) {
        int t = __shfl_up_sync(0xffffffffu, inc, off);
        if (lane >= off) inc += t;
    }
    *total = __shfl_sync(0xffffffffu, inc, 31);
    return inc - v;
}

// A: per-block reduce of 256 counts -> g_part[b]
__global__ void scan_reduce_kernel(int Nn)
{
    const int i = blockIdx.x * SCAN_B + threadIdx.x;
    int v = (i < Nn) ? g_cnt[i] : 0;
    #pragma unroll
    for (int off = 16; off > 0; off >>= 1)
        v += __shfl_down_sync(0xffffffffu, v, off);
    __shared__ int ws[8];
    const int lane = threadIdx.x & 31, wid = threadIdx.x >> 5;
    if (lane == 0) ws[wid] = v;
    __syncthreads();
    if (wid == 0) {                      // whole warp 0 participates
        int s = (lane < 8) ? ws[lane] : 0;
        #pragma unroll
        for (int off = 4; off > 0; off >>= 1)
            s += __shfl_down_sync(0xffffffffu, s, off);
        if (lane == 0) g_part[blockIdx.x] = s;
    }
}

// B: per-block: redundantly scan partials in smem, then exclusive-scan
// own 256-count chunk, write g_roff/g_cur, zero g_cnt, set g_roff[Nn].
__global__ void scan_apply_kernel(int NB, int Nn)
{
    __shared__ int pex[SCAN_B];   // exclusive scan of partials
    __shared__ int wtot[8];
    const int t = threadIdx.x, lane = t & 31, wid = t >> 5;

    // --- scan the NB partials (all blocks redundantly) ---
    {
        int v = (t < NB) ? g_part[t] : 0;
        int wt;
        int ex = warp_excl_scan(v, lane, &wt);
        if (lane == 0) wtot[wid] = wt;
        __syncthreads();
        if (wid == 0) {
            int s = (lane < 8) ? wtot[lane] : 0;
            int st;
            int sex = warp_excl_scan(s, lane, &st);
            if (lane < 8) wtot[lane] = sex;
            if (lane == 0 && blockIdx.x == 0) g_roff[Nn] = st;  // total = E
        }
        __syncthreads();
        pex[t] = ex + wtot[wid];
        __syncthreads();
    }
    const int base = pex[blockIdx.x];
    __syncthreads();   // wtot reused below

    // --- scan own chunk ---
    const int i = blockIdx.x * SCAN_B + t;
    int v = (i < Nn) ? g_cnt[i] : 0;
    int wt;
    int ex = warp_excl_scan(v, lane, &wt);
    if (lane == 0) wtot[wid] = wt;
    __syncthreads();
    if (wid == 0) {
        int s = (lane < 8) ? wtot[lane] : 0;
        int st;
        int sex = warp_excl_scan(s, lane, &st);
        if (lane < 8) wtot[lane] = sex;
    }
    __syncthreads();
    if (i < Nn) {
        int off = base + wtot[wid] + ex;
        g_roff[i] = off;
        g_cur[i]  = off;
        g_cnt[i]  = 0;          // reset for next call (graph replay safe)
    }
}

__global__ void scatter_kernel(const int* __restrict__ ei, int Ee)
{
    int e = blockIdx.x * blockDim.x + threadIdx.x;
    if (e < Ee) {
        int src = ei[e];
        int dst = ei[Ee + e];
        int pos = atomicAdd(&g_cur[dst], 1);
        g_src[pos] = src;
    }
}

// ============================================================
// Attention: warp-per-node online softmax, 4-edge groups with
// src-prefetch software pipeline. k,v fp16.
// ============================================================
__device__ __forceinline__ float warp_dot16(float2 qv, float2 kv)
{
    float p = qv.x * kv.x + qv.y * kv.y;
    p += __shfl_xor_sync(0xffffffffu, p, 8);
    p += __shfl_xor_sync(0xffffffffu, p, 4);
    p += __shfl_xor_sync(0xffffffffu, p, 2);
    p += __shfl_xor_sync(0xffffffffu, p, 1);
    return p * 0.17677669529663687f;   // 1/sqrt(32)
}

__device__ __forceinline__ void os_update(float alpha, float2 vv,
                                          float& m, float& den, float2& acc)
{
    if (alpha > m) {
        const float scale = __expf(m - alpha);   // first iter: exp(-inf)=0
        den = den * scale + 1.0f;
        acc.x = acc.x * scale + vv.x;
        acc.y = acc.y * scale + vv.y;
        m = alpha;
    } else {
        const float wgt = __expf(alpha - m);
        den += wgt;
        acc.x += wgt * vv.x;
        acc.y += wgt * vv.y;
    }
}

__global__ void __launch_bounds__(256)
attn_kernel(float* __restrict__ out, int Nn)
{
    const int warp = (blockIdx.x * blockDim.x + threadIdx.x) >> 5;
    if (warp >= Nn) return;
    const int n = warp;
    const int lane = threadIdx.x & 31;
    const int base = (lane >> 4) * 32 + (lane & 15) * 2;   // offset in 64-elem row

    const float2 qv = *(const float2*)(g_q + n * HC + base);

    float m = -CUDART_INF_F;
    float den = 0.0f;
    float2 acc = make_float2(0.0f, 0.0f);

    const int e0 = g_roff[n];
    const int e1 = g_roff[n + 1];

    int e = e0;
    if (e + 4 <= e1) {
        int s0 = g_src[e + 0];
        int s1 = g_src[e + 1];
        int s2 = g_src[e + 2];
        int s3 = g_src[e + 3];
        for (;;) {
            const bool more = (e + 8 <= e1);
            int t0, t1, t2, t3;
            if (more) {                  // prefetch next group's src
                t0 = g_src[e + 4];
                t1 = g_src[e + 5];
                t2 = g_src[e + 6];
                t3 = g_src[e + 7];
            }
            const int r0 = s0 << 6, r1 = s1 << 6, r2 = s2 << 6, r3 = s3 << 6;
            const float2 k0 = __half22float2(*(const __half2*)(g_kh + r0 + base));
            const float2 k1 = __half22float2(*(const __half2*)(g_kh + r1 + base));
            const float2 k2 = __half22float2(*(const __half2*)(g_kh + r2 + base));
            const float2 k3 = __half22float2(*(const __half2*)(g_kh + r3 + base));
            const float2 v0 = __half22float2(*(const __half2*)(g_vh + r0 + base));
            const float2 v1 = __half22float2(*(const __half2*)(g_vh + r1 + base));
            const float2 v2 = __half22float2(*(const __half2*)(g_vh + r2 + base));
            const float2 v3 = __half22float2(*(const __half2*)(g_vh + r3 + base));

            const float a0 = warp_dot16(qv, k0);
            const float a1 = warp_dot16(qv, k1);
            const float a2 = warp_dot16(qv, k2);
            const float a3 = warp_dot16(qv, k3);

            os_update(a0, v0, m, den, acc);
            os_update(a1, v1, m, den, acc);
            os_update(a2, v2, m, den, acc);
            os_update(a3, v3, m, den, acc);

            e += 4;
            if (!more) break;
            s0 = t0; s1 = t1; s2 = t2; s3 = t3;
        }
    }
    for (; e < e1; e++) {
        const int r = g_src[e] << 6;
        const float2 kv = __half22float2(*(const __half2*)(g_kh + r + base));
        const float2 vv = __half22float2(*(const __half2*)(g_vh + r + base));
        const float a = warp_dot16(qv, kv);
        os_update(a, vv, m, den, acc);
    }

    if (den > 0.0f) {
        const float inv = 1.0f / den;
        float2* o = (float2*)(out + n * HC + base);
        float2 cur = *o;
        cur.x += acc.x * inv;
        cur.y += acc.y * inv;
        *o = cur;
    }
}

// ============================================================
// Launcher — kernel launches ONLY (graph-capture safe).
// gemm kept at launch index 3 (the ncu-profiled slot).
// ============================================================
extern "C" void kernel_launch(void* const* d_in, const int* in_sizes, int n_in,
                              void* d_out, int out_size)
{
    const float* x   = (const float*)d_in[0];
    const int*   ei  = (const int*)d_in[1];     // int32 (jax x64 disabled)
    const float* Wq  = (const float*)d_in[2];
    const float* bq  = (const float*)d_in[3];
    const float* Wk  = (const float*)d_in[4];
    const float* bk  = (const float*)d_in[5];
    const float* Wv  = (const float*)d_in[6];
    const float* bv  = (const float*)d_in[7];
    const float* Wsk = (const float*)d_in[8];
    const float* bsk = (const float*)d_in[9];
    float* out = (float*)d_out;

    const int Nn = in_sizes[0] / DIN;
    const int Ee = in_sizes[1] / 2;
    const int NB = (Nn + SCAN_B - 1) / SCAN_B;

    // CSR build by destination node
    hist_kernel<<<(Ee + 255) / 256, 256>>>(ei, Ee);               // 0
    scan_reduce_kernel<<<NB, SCAN_B>>>(Nn);                        // 1
    scan_apply_kernel<<<NB, SCAN_B>>>(NB, Nn);                     // 2

    // GEMMs (independent of CSR): g_q, g_kh, g_vh, skip -> d_out   // 3 (profiled)
    gemm_qkvs_kernel<<<(Nn + 31) / 32, 256>>>(
        x, Wq, bq, Wk, bk, Wv, bv, Wsk, bsk, out, Nn);

    scatter_kernel<<<(Ee + 255) / 256, 256>>>(ei, Ee);             // 4

    // attention: one warp per destination node, accumulates into d_out
    attn_kernel<<<(Nn * 32 + 255) / 256, 256>>>(out, Nn);          // 5
}